// round 7
// baseline (speedup 1.0000x reference)
#include <cuda_runtime.h>
#include <cuda_bf16.h>
#include <math.h>
#include <stdint.h>

// ---------------------------------------------------------------------------
// EBT_GRC beam search. N=256, S=32, D=512, CH=2048, BEAM=5.
// All GEMMs: bf16 triple-split (3 planes/operand, 6 cross-products) on
// mma.sync.m16n8k16 tensor cores => fp32-equivalent accuracy.
// R7: cp.async double-buffered pipeline + hoisted fragment loads in gemm6.
// ---------------------------------------------------------------------------

#define NB    256
#define SEQ   32
#define DIM   512
#define CH    2048
#define BEAMK 5
#define MAXR  192
#define NTASK (NB * BEAMK)

typedef __nv_bfloat16 bhalf;

// fp32 state
__device__ float g_rows[NB * MAXR * DIM];
__device__ float g_u  [NB * MAXR * DIM];
__device__ float g_v  [NB * MAXR * DIM];
__device__ float g_tmp[NB * SEQ * DIM];
__device__ float g_cc [NTASK * CH];
__device__ int   g_idx [NB * BEAMK * SEQ];
__device__ float g_accu[NB * BEAMK];
__device__ int   g_task_l[NTASK];
__device__ int   g_task_r[NTASK];
// bf16 triple-split planes
__device__ bhalf g_rp0[NB * MAXR * DIM], g_rp1[NB * MAXR * DIM], g_rp2[NB * MAXR * DIM];
__device__ bhalf g_xp0[NB * SEQ * DIM],  g_xp1[NB * SEQ * DIM],  g_xp2[NB * SEQ * DIM];
__device__ bhalf g_hp0[NTASK * CH],      g_hp1[NTASK * CH],      g_hp2[NTASK * CH];
__device__ bhalf g_wi0[DIM * DIM],       g_wi1[DIM * DIM],       g_wi2[DIM * DIM];
__device__ bhalf g_wdp0[DIM * 2 * DIM],  g_wdp1[DIM * 2 * DIM],  g_wdp2[DIM * 2 * DIM];
__device__ bhalf g_wc1p0[2 * DIM * CH],  g_wc1p1[2 * DIM * CH],  g_wc1p2[2 * DIM * CH];
__device__ bhalf g_wc2p0[CH * CH],       g_wc2p1[CH * CH],       g_wc2p2[CH * CH];

__device__ __forceinline__ float gelu_f(float xval) {
    return 0.5f * xval * (1.0f + erff(xval * 0.70710678118654752440f));
}
__device__ __forceinline__ void split3(float xval, unsigned short &qs0,
                                       unsigned short &qs1, unsigned short &qs2) {
    bhalf h0 = __float2bfloat16(xval);
    float r0 = __bfloat162float(h0);
    bhalf h1 = __float2bfloat16(xval - r0);
    float r1 = __bfloat162float(h1);
    bhalf h2 = __float2bfloat16(xval - r0 - r1);
    qs0 = __bfloat16_as_ushort(h0);
    qs1 = __bfloat16_as_ushort(h1);
    qs2 = __bfloat16_as_ushort(h2);
}

__device__ __forceinline__ void ldmA(uint32_t regs[4], uint32_t addr) {
    asm volatile("ldmatrix.sync.aligned.m8n8.x4.shared.b16 {%0,%1,%2,%3}, [%4];"
        : "=r"(regs[0]), "=r"(regs[1]), "=r"(regs[2]), "=r"(regs[3]) : "r"(addr));
}
__device__ __forceinline__ void ldmBT(uint32_t regs[4], uint32_t addr) {
    asm volatile("ldmatrix.sync.aligned.m8n8.x4.trans.shared.b16 {%0,%1,%2,%3}, [%4];"
        : "=r"(regs[0]), "=r"(regs[1]), "=r"(regs[2]), "=r"(regs[3]) : "r"(addr));
}
__device__ __forceinline__ void mma16816(float cfr[4], const uint32_t afr[4],
                                         uint32_t rblo, uint32_t rbhi) {
    asm volatile(
        "mma.sync.aligned.m16n8k16.row.col.f32.bf16.bf16.f32 "
        "{%0,%1,%2,%3}, {%4,%5,%6,%7}, {%8,%9}, {%0,%1,%2,%3};"
        : "+f"(cfr[0]), "+f"(cfr[1]), "+f"(cfr[2]), "+f"(cfr[3])
        : "r"(afr[0]), "r"(afr[1]), "r"(afr[2]), "r"(afr[3]), "r"(rblo), "r"(rbhi));
}
__device__ __forceinline__ void cp16(uint32_t saddr, const void* gaddr) {
    asm volatile("cp.async.cg.shared.global [%0], [%1], 16;"
                 :: "r"(saddr), "l"(gaddr));
}
__device__ __forceinline__ void cp_commit() {
    asm volatile("cp.async.commit_group;");
}
template <int WG>
__device__ __forceinline__ void cp_wait() {
    asm volatile("cp.async.wait_group %0;" :: "n"(WG));
}

// ------------------------------ mma GEMM ------------------------------------
// Tile 128x128x32, 512 threads (16 warps, 4m x 4n), warp tile 32x32.
// Double-buffered cp.async stages; hoisted ldmatrix per ks.
#define BM 128
#define BN 128
#define BK 32
#define BKP 40     // A smem row stride (bf16 elems); 80B rows (16B multiple)
#define BNP 136    // B smem row stride; 272B rows
#define PLA (BM * BKP)            // 5120 elems per A plane
#define PLB (BK * BNP)            // 4352 elems per B plane
#define STG (3 * PLA + 3 * PLB)   // 28416 elems per stage
#define SMEM_BYTES (2 * STG * 2)  // 113664 bytes

// a_mode: 0 contiguous lda; 1 row-pool (base,rpn); 2 cat-gather (task_l/r, K=1024)
// c_mode: 0 fp32 contiguous ldc; 1 fp32 row-pool split at n_split (Cf/Cf2); 2 planes
__global__ __launch_bounds__(512) void gemm6(
    const bhalf* __restrict__ A0, const bhalf* __restrict__ A1, const bhalf* __restrict__ A2,
    const bhalf* __restrict__ B0, const bhalf* __restrict__ B1, const bhalf* __restrict__ B2,
    const float* __restrict__ bias, float* __restrict__ Cf, float* __restrict__ Cf2,
    bhalf* __restrict__ P0, bhalf* __restrict__ P1, bhalf* __restrict__ P2,
    int K, int lda, int ldb, int ldc,
    int a_mode, int a_base, int a_rpn,
    int c_mode, int c_base, int c_rpn, int act, int n_split)
{
    extern __shared__ __align__(16) bhalf smem[];

    const int tid = threadIdx.x;
    const int lane = tid & 31, wrp = tid >> 5;
    const int m0 = blockIdx.y * BM;
    const int n0b = blockIdx.x * BN;
    const int m_w = (wrp >> 2) * 32;
    const int n_w = (wrp & 3) * 32;

    // loader: A -> one 16B chunk per plane per thread (128 rows x 4 k-chunks)
    //         B -> one 16B chunk per plane per thread (32 rows x 16 n-chunks)
    const int arow = tid >> 2, ak8 = (tid & 3) << 3;
    const int brow = tid >> 4, bn8 = (tid & 15) << 3;
    int aL = 0, aR = 0;
    {
        int mrow = m0 + arow;
        if (a_mode == 0) aL = mrow * lda + ak8;
        else if (a_mode == 1) {
            int nz = mrow / a_rpn, rr = mrow - nz * a_rpn;
            aL = (nz * MAXR + a_base + rr) * DIM + ak8;
        } else {
            int nz = mrow / BEAMK;
            aL = (nz * MAXR + g_task_l[mrow]) * DIM + ak8;
            aR = (nz * MAXR + g_task_r[mrow]) * DIM + ak8;
        }
    }
    const int boff = brow * ldb + n0b + bn8;
    const uint32_t smem_u = (uint32_t)__cvta_generic_to_shared(smem);
    const uint32_t asw = (uint32_t)(arow * BKP + ak8) * 2;
    const uint32_t bsw = (uint32_t)(3 * PLA + brow * BNP + bn8) * 2;

    auto issue_stage = [&](int stg, int kbase) {
        uint32_t sb = smem_u + (uint32_t)stg * (STG * 2);
        int ao;
        if (a_mode == 2)
            ao = (kbase + ak8 < DIM) ? (aL + kbase) : (aR + kbase - DIM);
        else
            ao = aL + kbase;
        cp16(sb + 0 * (PLA * 2) + asw, A0 + ao);
        cp16(sb + 1 * (PLA * 2) + asw, A1 + ao);
        cp16(sb + 2 * (PLA * 2) + asw, A2 + ao);
        int bo = boff + kbase * ldb;
        cp16(sb + bsw + 0 * (PLB * 2), B0 + bo);
        cp16(sb + bsw + 1 * (PLB * 2), B1 + bo);
        cp16(sb + bsw + 2 * (PLB * 2), B2 + bo);
    };

    float acc[2][4][4];
#pragma unroll
    for (int mt = 0; mt < 2; mt++)
#pragma unroll
        for (int nt = 0; nt < 4; nt++)
#pragma unroll
            for (int qq = 0; qq < 4; qq++) acc[mt][nt][qq] = 0.f;

    const int KT = K / BK;
    issue_stage(0, 0);
    cp_commit();

    const int lrow16 = lane & 15, lcol8 = (lane >> 4) << 3;

    for (int kt = 0; kt < KT; kt++) {
        if (kt + 1 < KT) {
            issue_stage((kt + 1) & 1, (kt + 1) * BK);
            cp_commit();
            cp_wait<1>();
        } else {
            cp_wait<0>();
        }
        __syncthreads();

        uint32_t sb = smem_u + (uint32_t)(kt & 1) * (STG * 2);
#pragma unroll
        for (int ks = 0; ks < 2; ks++) {
            uint32_t frag_a[3][2][4];
            uint32_t frag_b[3][2][4];
#pragma unroll
            for (int pl = 0; pl < 3; pl++) {
#pragma unroll
                for (int mt = 0; mt < 2; mt++)
                    ldmA(frag_a[pl][mt],
                         sb + (uint32_t)(pl * PLA + (m_w + mt * 16 + lrow16) * BKP
                                         + ks * 16 + lcol8) * 2);
#pragma unroll
                for (int nb = 0; nb < 2; nb++)
                    ldmBT(frag_b[pl][nb],
                          sb + (uint32_t)(3 * PLA + pl * PLB
                                          + (ks * 16 + lrow16) * BNP
                                          + n_w + nb * 16 + lcol8) * 2);
            }
#pragma unroll
            for (int pA = 0; pA < 3; pA++) {
#pragma unroll
                for (int pB = 0; pB < 3; pB++) {
                    if (pA + pB < 3) {
#pragma unroll
                        for (int mt = 0; mt < 2; mt++)
#pragma unroll
                            for (int nt = 0; nt < 4; nt++)
                                mma16816(acc[mt][nt], frag_a[pA][mt],
                                         frag_b[pB][nt >> 1][(nt & 1) * 2],
                                         frag_b[pB][nt >> 1][(nt & 1) * 2 + 1]);
                    }
                }
            }
        }
        __syncthreads();
    }

    // ------------------------------ epilogue --------------------------------
    float* Cfx = Cf;
    int n0c = n0b;
    if (c_mode == 1 && n0b >= n_split) { Cfx = Cf2; n0c = n0b - n_split; }

    const int grp = lane >> 2, tc2 = (lane & 3) * 2;
#pragma unroll
    for (int mt = 0; mt < 2; mt++) {
#pragma unroll
        for (int nt = 0; nt < 4; nt++) {
            int coln = n_w + nt * 8 + tc2;
            float2 bv = make_float2(0.f, 0.f);
            if (bias) bv = *(const float2*)(bias + n0b + coln);
            float vals[2][2];
            vals[0][0] = acc[mt][nt][0] + bv.x; vals[0][1] = acc[mt][nt][1] + bv.y;
            vals[1][0] = acc[mt][nt][2] + bv.x; vals[1][1] = acc[mt][nt][3] + bv.y;
            if (act) {
#pragma unroll
                for (int hh = 0; hh < 2; hh++) {
                    vals[hh][0] = gelu_f(vals[hh][0]);
                    vals[hh][1] = gelu_f(vals[hh][1]);
                }
            }
#pragma unroll
            for (int hh = 0; hh < 2; hh++) {
                int mrow = m0 + m_w + mt * 16 + grp + hh * 8;
                if (c_mode == 2) {
                    size_t off = (size_t)mrow * ldc + n0b + coln;
                    unsigned short plo0, plo1, plo2, phi0, phi1, phi2;
                    split3(vals[hh][0], plo0, plo1, plo2);
                    split3(vals[hh][1], phi0, phi1, phi2);
                    *(uint32_t*)(P0 + off) = (uint32_t)plo0 | ((uint32_t)phi0 << 16);
                    *(uint32_t*)(P1 + off) = (uint32_t)plo1 | ((uint32_t)phi1 << 16);
                    *(uint32_t*)(P2 + off) = (uint32_t)plo2 | ((uint32_t)phi2 << 16);
                } else if (c_mode == 1) {
                    int nz = mrow / c_rpn, rr = mrow - nz * c_rpn;
                    float* cp = Cfx + ((size_t)nz * MAXR + c_base + rr) * DIM + n0c + coln;
                    *(float2*)cp = make_float2(vals[hh][0], vals[hh][1]);
                } else {
                    float* cp = Cfx + (size_t)mrow * ldc + n0b + coln;
                    *(float2*)cp = make_float2(vals[hh][0], vals[hh][1]);
                }
            }
        }
    }
}

// --------------------------- pack kernels -----------------------------------
__global__ void pack3_kernel(const float* __restrict__ src,
                             bhalf* __restrict__ dst0, bhalf* __restrict__ dst1,
                             bhalf* __restrict__ dst2, int nelem)
{
    for (int i = blockIdx.x * blockDim.x + threadIdx.x; i < nelem;
         i += gridDim.x * blockDim.x) {
        unsigned short qs0, qs1, qs2;
        split3(src[i], qs0, qs1, qs2);
        dst0[i] = __ushort_as_bfloat16(qs0);
        dst1[i] = __ushort_as_bfloat16(qs1);
        dst2[i] = __ushort_as_bfloat16(qs2);
    }
}
// Wd1 (1024,512) -> B' [512][1024]: B'[k][n] = Wd1[(n<512?k:512+k)][n&511]
__global__ void pack3_wd1_kernel(const float* __restrict__ src,
                                 bhalf* __restrict__ dst0, bhalf* __restrict__ dst1,
                                 bhalf* __restrict__ dst2)
{
    for (int i = blockIdx.x * blockDim.x + threadIdx.x; i < DIM * 2 * DIM;
         i += gridDim.x * blockDim.x) {
        int krow = i >> 10, ncol = i & 1023;
        float xval = src[(ncol < DIM ? krow : DIM + krow) * DIM + (ncol & (DIM - 1))];
        unsigned short qs0, qs1, qs2;
        split3(xval, qs0, qs1, qs2);
        dst0[i] = __ushort_as_bfloat16(qs0);
        dst1[i] = __ushort_as_bfloat16(qs1);
        dst2[i] = __ushort_as_bfloat16(qs2);
    }
}

// ------------------------ selection (per batch elem) ------------------------
__global__ __launch_bounds__(256) void select_kernel(
    int Bc, int S_cur, int topk, int base_dest,
    const float* __restrict__ bd1, const float* __restrict__ Wd2,
    const float* __restrict__ bd2)
{
    const int nn = blockIdx.x;
    const int tid = threadIdx.x;
    __shared__ float sw[BEAMK][SEQ];
    __shared__ int   sold[BEAMK][SEQ];
    __shared__ int   snew[BEAMK][SEQ];
    __shared__ float saccu[BEAMK];
    __shared__ float cscore[BEAMK * BEAMK];
    __shared__ int   cparent[BEAMK * BEAMK];
    __shared__ int   cpos[BEAMK * BEAMK];
    __shared__ int   ssel[BEAMK];
    __shared__ float snacc[BEAMK];
    __shared__ float sbd1[DIM];
    __shared__ float swd2[DIM];

    for (int t = tid; t < Bc * (S_cur + 1); t += 256) {
        int bb = t / (S_cur + 1), ss = t - bb * (S_cur + 1);
        sold[bb][ss] = g_idx[(nn * BEAMK + bb) * SEQ + ss];
    }
    for (int dd = tid; dd < DIM; dd += 256) { sbd1[dd] = bd1[dd]; swd2[dd] = Wd2[dd]; }
    if (tid < Bc) saccu[tid] = g_accu[nn * BEAMK + tid];
    __syncthreads();

    if (S_cur == 1) {
        if (tid < Bc) {
            g_task_l[nn * BEAMK + tid] = sold[tid][0];
            g_task_r[nn * BEAMK + tid] = sold[tid][1];
            g_idx[(nn * BEAMK + tid) * SEQ] = base_dest + tid;
        }
        return;
    }

    const int lane = tid & 31, wrp = tid >> 5;
    const float* un = g_u + (size_t)nn * MAXR * DIM;
    const float* vn = g_v + (size_t)nn * MAXR * DIM;
    for (int pp = wrp; pp < Bc * S_cur; pp += 8) {
        int bb = pp / S_cur, ss = pp - bb * S_cur;
        const float* ul = un + (size_t)sold[bb][ss] * DIM;
        const float* vr = vn + (size_t)sold[bb][ss + 1] * DIM;
        float accv = 0.f;
        for (int dd = lane; dd < DIM; dd += 32)
            accv += gelu_f(ul[dd] + vr[dd] + sbd1[dd]) * swd2[dd];
#pragma unroll
        for (int oo = 16; oo; oo >>= 1)
            accv += __shfl_xor_sync(0xffffffffu, accv, oo);
        if (lane == 0) sw[bb][ss] = accv + bd2[0];
    }
    __syncthreads();

    if (tid < Bc) {
        int bb = tid;
        float mx = -1e30f;
        for (int ss = 0; ss < S_cur; ss++) mx = fmaxf(mx, sw[bb][ss]);
        float sum = 0.f;
        for (int ss = 0; ss < S_cur; ss++) sum += expf(sw[bb][ss] - mx);
        sum += 1e-20f;
        unsigned used = 0u;
        for (int kk = 0; kk < topk; kk++) {
            float bestv = -1e30f; int besti = 0;
            for (int ss = 0; ss < S_cur; ss++) {
                if (used & (1u << ss)) continue;
                if (sw[bb][ss] > bestv) { bestv = sw[bb][ss]; besti = ss; }
            }
            used |= 1u << besti;
            float soft = expf(bestv - mx) / sum;
            cscore [bb * topk + kk] = saccu[bb] + logf(soft + 1e-20f);
            cparent[bb * topk + kk] = bb;
            cpos   [bb * topk + kk] = besti;
        }
    }
    __syncthreads();

    if (tid == 0) {
        int nc = Bc * topk;
        if (nc <= BEAMK) {
            for (int kk = 0; kk < nc; kk++) ssel[kk] = kk;
        } else {
            unsigned used = 0u;
            for (int kk = 0; kk < BEAMK; kk++) {
                float bestv = -1e30f; int besti = 0;
                for (int cc = 0; cc < nc; cc++) {
                    if (used & (1u << cc)) continue;
                    if (cscore[cc] > bestv) { bestv = cscore[cc]; besti = cc; }
                }
                used |= 1u << besti;
                ssel[kk] = besti;
            }
        }
    }
    __syncthreads();

    if (tid < BEAMK) {
        int cc = ssel[tid];
        snacc[tid] = cscore[cc];
        int pp = cparent[cc], jj = cpos[cc];
        g_task_l[nn * BEAMK + tid] = sold[pp][jj];
        g_task_r[nn * BEAMK + tid] = sold[pp][jj + 1];
    }
    __syncthreads();
    for (int t = tid; t < BEAMK * S_cur; t += 256) {
        int kk = t / S_cur, ss = t - kk * S_cur;
        int cc = ssel[kk]; int pp = cparent[cc], jj = cpos[cc];
        snew[kk][ss] = (ss < jj) ? sold[pp][ss]
                                 : (ss == jj ? base_dest + kk : sold[pp][ss + 1]);
    }
    __syncthreads();
    for (int t = tid; t < BEAMK * S_cur; t += 256) {
        int kk = t / S_cur, ss = t - kk * S_cur;
        g_idx[(nn * BEAMK + kk) * SEQ + ss] = snew[kk][ss];
    }
    if (tid < BEAMK) g_accu[nn * BEAMK + tid] = snacc[tid];
}

// ---------------------- gating + layernorm epilogue -------------------------
__global__ __launch_bounds__(256) void gate_ln_kernel(
    int base_dest, const float* __restrict__ gw, const float* __restrict__ bw)
{
    const int t = blockIdx.x;
    const int nn = t / BEAMK;
    const int kk = t - nn * BEAMK;
    const int tid = threadIdx.x;
    const float* cc   = g_cc   + (size_t)t * CH;
    const float* lrow = g_rows + ((size_t)nn * MAXR + g_task_l[t]) * DIM;
    const float* rrow = g_rows + ((size_t)nn * MAXR + g_task_r[t]) * DIM;
    __shared__ float sout[DIM];
    __shared__ float red[2][8];
    float lsum = 0.f, lsq = 0.f;
#pragma unroll
    for (int it = 0; it < 2; it++) {
        int dd = tid + it * 256;
        float c0v = cc[dd], c1v = cc[DIM + dd], c2v = cc[2 * DIM + dd], c3v = cc[3 * DIM + dd];
        float mx = fmaxf(c0v, fmaxf(c1v, c2v));
        float e0v = expf(c0v - mx), e1v = expf(c1v - mx), e2v = expf(c2v - mx);
        float inv = 1.0f / (e0v + e1v + e2v);
        float ov = (e0v * lrow[dd] + e1v * rrow[dd] + e2v * c3v) * inv;
        sout[dd] = ov; lsum += ov; lsq += ov * ov;
    }
#pragma unroll
    for (int oo = 16; oo; oo >>= 1) {
        lsum += __shfl_xor_sync(0xffffffffu, lsum, oo);
        lsq  += __shfl_xor_sync(0xffffffffu, lsq , oo);
    }
    if ((tid & 31) == 0) { red[0][tid >> 5] = lsum; red[1][tid >> 5] = lsq; }
    __syncthreads();
    if (tid < 32) {
        float ra = (tid < 8) ? red[0][tid] : 0.f;
        float rb = (tid < 8) ? red[1][tid] : 0.f;
#pragma unroll
        for (int oo = 4; oo; oo >>= 1) {
            ra += __shfl_xor_sync(0xffffffffu, ra, oo);
            rb += __shfl_xor_sync(0xffffffffu, rb, oo);
        }
        if (tid == 0) { red[0][0] = ra; red[1][0] = rb; }
    }
    __syncthreads();
    float mu   = red[0][0] * (1.0f / DIM);
    float var  = red[1][0] * (1.0f / DIM) - mu * mu;
    float rstd = rsqrtf(var + 1e-5f);
    size_t ro = ((size_t)nn * MAXR + base_dest + kk) * DIM;
#pragma unroll
    for (int it = 0; it < 2; it++) {
        int dd = tid + it * 256;
        float ov = (sout[dd] - mu) * rstd * gw[dd] + bw[dd];
        g_rows[ro + dd] = ov;
        unsigned short qs0, qs1, qs2;
        split3(ov, qs0, qs1, qs2);
        g_rp0[ro + dd] = __ushort_as_bfloat16(qs0);
        g_rp1[ro + dd] = __ushort_as_bfloat16(qs1);
        g_rp2[ro + dd] = __ushort_as_bfloat16(qs2);
    }
}

// --------------------- init: layernorm of x@Wi+bi ---------------------------
__global__ __launch_bounds__(256) void ln_init_kernel(
    const float* __restrict__ gw, const float* __restrict__ bw)
{
    const int t = blockIdx.x;
    const int nn = t >> 5, ss = t & 31;
    const int tid = threadIdx.x;
    const float* inp = g_tmp + (size_t)t * DIM;
    size_t ro = ((size_t)nn * MAXR + ss) * DIM;
    __shared__ float red[2][8];
    float v0 = inp[tid], v1 = inp[tid + 256];
    float lsum = v0 + v1, lsq = v0 * v0 + v1 * v1;
#pragma unroll
    for (int oo = 16; oo; oo >>= 1) {
        lsum += __shfl_xor_sync(0xffffffffu, lsum, oo);
        lsq  += __shfl_xor_sync(0xffffffffu, lsq , oo);
    }
    if ((tid & 31) == 0) { red[0][tid >> 5] = lsum; red[1][tid >> 5] = lsq; }
    __syncthreads();
    if (tid < 32) {
        float ra = (tid < 8) ? red[0][tid] : 0.f;
        float rb = (tid < 8) ? red[1][tid] : 0.f;
#pragma unroll
        for (int oo = 4; oo; oo >>= 1) {
            ra += __shfl_xor_sync(0xffffffffu, ra, oo);
            rb += __shfl_xor_sync(0xffffffffu, rb, oo);
        }
        if (tid == 0) { red[0][0] = ra; red[1][0] = rb; }
    }
    __syncthreads();
    float mu   = red[0][0] * (1.0f / DIM);
    float var  = red[1][0] * (1.0f / DIM) - mu * mu;
    float rstd = rsqrtf(var + 1e-5f);
#pragma unroll
    for (int it = 0; it < 2; it++) {
        int dd = tid + it * 256;
        float vv = it ? v1 : v0;
        float ov = (vv - mu) * rstd * gw[dd] + bw[dd];
        g_rows[ro + dd] = ov;
        unsigned short qs0, qs1, qs2;
        split3(ov, qs0, qs1, qs2);
        g_rp0[ro + dd] = __ushort_as_bfloat16(qs0);
        g_rp1[ro + dd] = __ushort_as_bfloat16(qs1);
        g_rp2[ro + dd] = __ushort_as_bfloat16(qs2);
    }
}

__global__ void init_state_kernel()
{
    int nn = blockIdx.x;
    if (threadIdx.x < SEQ) g_idx[nn * BEAMK * SEQ + threadIdx.x] = threadIdx.x;
    if (threadIdx.x == 0) g_accu[nn * BEAMK] = 0.f;
}

__global__ __launch_bounds__(256) void final_kernel(float* __restrict__ outp)
{
    const int nn = blockIdx.x;
    const int tid = threadIdx.x;
    __shared__ float wts[BEAMK];
    __shared__ int   rid[BEAMK];
    if (tid < BEAMK) rid[tid] = g_idx[(nn * BEAMK + tid) * SEQ];
    if (tid == 0) {
        float av[BEAMK]; float mx = -1e30f;
        for (int bb = 0; bb < BEAMK; bb++) {
            av[bb] = g_accu[nn * BEAMK + bb]; mx = fmaxf(mx, av[bb]);
        }
        float sm = 0.f;
        for (int bb = 0; bb < BEAMK; bb++) { av[bb] = expf(av[bb] - mx); sm += av[bb]; }
        for (int bb = 0; bb < BEAMK; bb++) wts[bb] = av[bb] / sm;
    }
    __syncthreads();
#pragma unroll
    for (int it = 0; it < 2; it++) {
        int dd = tid + it * 256;
        float accv = 0.f;
        for (int bb = 0; bb < BEAMK; bb++)
            accv += wts[bb] * g_rows[((size_t)nn * MAXR + rid[bb]) * DIM + dd];
        outp[nn * DIM + dd] = accv;
    }
}

// --------------------------------- host ------------------------------------
extern "C" void kernel_launch(void* const* d_in, const int* in_sizes, int n_in,
                              void* d_out, int out_size)
{
    const float* x   = (const float*)d_in[0];
    const float* Wi  = (const float*)d_in[2];
    const float* bi  = (const float*)d_in[3];
    const float* g1  = (const float*)d_in[4];
    const float* b1  = (const float*)d_in[5];
    const float* Wd1 = (const float*)d_in[6];
    const float* bd1 = (const float*)d_in[7];
    const float* Wd2 = (const float*)d_in[8];
    const float* bd2 = (const float*)d_in[9];
    const float* Wc1 = (const float*)d_in[10];
    const float* bc1 = (const float*)d_in[11];
    const float* Wc2 = (const float*)d_in[12];
    const float* bc2 = (const float*)d_in[13];
    const float* g2  = (const float*)d_in[14];
    const float* b2  = (const float*)d_in[15];
    float* outp = (float*)d_out;

    cudaFuncSetAttribute(gemm6, cudaFuncAttributeMaxDynamicSharedMemorySize,
                         SMEM_BYTES);

    float *tmp_p, *u_p, *v_p, *cc_p;
    cudaGetSymbolAddress((void**)&tmp_p, g_tmp);
    cudaGetSymbolAddress((void**)&u_p,   g_u);
    cudaGetSymbolAddress((void**)&v_p,   g_v);
    cudaGetSymbolAddress((void**)&cc_p,  g_cc);
    bhalf *rp0, *rp1, *rp2, *xp0, *xp1, *xp2, *hp0, *hp1, *hp2;
    bhalf *wi0, *wi1, *wi2, *wd0, *wd1p, *wd2p;
    bhalf *wc10, *wc11, *wc12, *wc20, *wc21, *wc22;
    cudaGetSymbolAddress((void**)&rp0, g_rp0);
    cudaGetSymbolAddress((void**)&rp1, g_rp1);
    cudaGetSymbolAddress((void**)&rp2, g_rp2);
    cudaGetSymbolAddress((void**)&xp0, g_xp0);
    cudaGetSymbolAddress((void**)&xp1, g_xp1);
    cudaGetSymbolAddress((void**)&xp2, g_xp2);
    cudaGetSymbolAddress((void**)&hp0, g_hp0);
    cudaGetSymbolAddress((void**)&hp1, g_hp1);
    cudaGetSymbolAddress((void**)&hp2, g_hp2);
    cudaGetSymbolAddress((void**)&wi0, g_wi0);
    cudaGetSymbolAddress((void**)&wi1, g_wi1);
    cudaGetSymbolAddress((void**)&wi2, g_wi2);
    cudaGetSymbolAddress((void**)&wd0,  g_wdp0);
    cudaGetSymbolAddress((void**)&wd1p, g_wdp1);
    cudaGetSymbolAddress((void**)&wd2p, g_wdp2);
    cudaGetSymbolAddress((void**)&wc10, g_wc1p0);
    cudaGetSymbolAddress((void**)&wc11, g_wc1p1);
    cudaGetSymbolAddress((void**)&wc12, g_wc1p2);
    cudaGetSymbolAddress((void**)&wc20, g_wc2p0);
    cudaGetSymbolAddress((void**)&wc21, g_wc2p1);
    cudaGetSymbolAddress((void**)&wc22, g_wc2p2);

    // pack inputs & weights into triple-split planes
    pack3_kernel<<<512, 256>>>(x,   xp0, xp1, xp2, NB * SEQ * DIM);
    pack3_kernel<<<256, 256>>>(Wi,  wi0, wi1, wi2, DIM * DIM);
    pack3_wd1_kernel<<<256, 256>>>(Wd1, wd0, wd1p, wd2p);
    pack3_kernel<<<512, 256>>>(Wc1, wc10, wc11, wc12, 2 * DIM * CH);
    pack3_kernel<<<512, 256>>>(Wc2, wc20, wc21, wc22, CH * CH);

    dim3 blk(512);
    // init GEMM: tmp = x@Wi+bi  (M=8192, N=512, K=512)
    gemm6<<<dim3(DIM / BN, (NB * SEQ) / BM), blk, SMEM_BYTES>>>(
        xp0, xp1, xp2, wi0, wi1, wi2, bi, tmp_p, nullptr,
        nullptr, nullptr, nullptr,
        DIM, DIM, DIM, DIM, 0, 0, 0, 0, 0, 0, 0, 0);
    ln_init_kernel<<<NB * SEQ, 256>>>(g1, b1);
    init_state_kernel<<<NB, 32>>>();
    // u|v projection of initial rows (M=8192, N=1024, K=512)
    gemm6<<<dim3(2 * DIM / BN, (NB * SEQ) / BM), blk, SMEM_BYTES>>>(
        rp0, rp1, rp2, wd0, wd1p, wd2p, nullptr, u_p, v_p,
        nullptr, nullptr, nullptr,
        DIM, 0, 2 * DIM, DIM, 1, 0, SEQ, 1, 0, SEQ, 0, DIM);

    for (int step = 0; step < SEQ - 1; step++) {
        int S_cur = (SEQ - 1) - step;
        int Bc = (step == 0) ? 1 : BEAMK;
        int topk = S_cur < BEAMK ? S_cur : BEAMK;
        int base = SEQ + step * BEAMK;

        select_kernel<<<NB, 256>>>(Bc, S_cur, topk, base, bd1, Wd2, bd2);
        // cat GEMM: gelu([l|r]@Wc1+bc1) -> hcat planes (M=1280,N=2048,K=1024)
        gemm6<<<dim3(CH / BN, NTASK / BM), blk, SMEM_BYTES>>>(
            rp0, rp1, rp2, wc10, wc11, wc12, bc1, nullptr, nullptr,
            hp0, hp1, hp2,
            2 * DIM, 0, CH, CH, 2, 0, 0, 2, 0, 0, 1, 0);
        // GEMM2: cc = hcat@Wc2+bc2  (M=1280, N=2048, K=2048)
        gemm6<<<dim3(CH / BN, NTASK / BM), blk, SMEM_BYTES>>>(
            hp0, hp1, hp2, wc20, wc21, wc22, bc2, cc_p, nullptr,
            nullptr, nullptr, nullptr,
            CH, CH, CH, CH, 0, 0, 0, 0, 0, 0, 0, 0);
        gate_ln_kernel<<<NTASK, 256>>>(base, g2, b2);
        if (step < SEQ - 2) {
            // u|v projection of new rows (M=1280, N=1024, K=512)
            gemm6<<<dim3(2 * DIM / BN, NTASK / BM), blk, SMEM_BYTES>>>(
                rp0, rp1, rp2, wd0, wd1p, wd2p, nullptr, u_p, v_p,
                nullptr, nullptr, nullptr,
                DIM, 0, 2 * DIM, DIM, 1, base, BEAMK, 1, base, BEAMK, 0, DIM);
        }
    }

    final_kernel<<<NB, 256>>>(outp);
    (void)in_sizes; (void)n_in; (void)out_size;
}

// round 9
// speedup vs baseline: 1.2032x; 1.2032x over previous
#include <cuda_runtime.h>
#include <cuda_bf16.h>
#include <math.h>
#include <stdint.h>

// ---------------------------------------------------------------------------
// EBT_GRC beam search. N=256, S=32, D=512, CH=2048, BEAM=5.
// GEMMs: bf16 3-split (3 planes/operand, 6 cross-products) on
// mma.sync.m16n8k16 => fp32-equivalent accuracy (proven in R6).
// R9: BM=128/BN=64 tiles, 256 threads, 2 CTA/SM, cp.async double buffer.
// ---------------------------------------------------------------------------

#define NB    256
#define SEQ   32
#define DIM   512
#define CH    2048
#define BEAMK 5
#define MAXR  192
#define NTASK (NB * BEAMK)

typedef __nv_bfloat16 bhalf;

// fp32 state
__device__ float g_rows[NB * MAXR * DIM];
__device__ float g_u  [NB * MAXR * DIM];
__device__ float g_v  [NB * MAXR * DIM];
__device__ float g_tmp[NB * SEQ * DIM];
__device__ float g_cc [NTASK * CH];
__device__ int   g_idx [NB * BEAMK * SEQ];
__device__ float g_accu[NB * BEAMK];
__device__ int   g_task_l[NTASK];
__device__ int   g_task_r[NTASK];
// bf16 3-split planes
__device__ bhalf g_rp0[NB * MAXR * DIM], g_rp1[NB * MAXR * DIM], g_rp2[NB * MAXR * DIM];
__device__ bhalf g_xp0[NB * SEQ * DIM],  g_xp1[NB * SEQ * DIM],  g_xp2[NB * SEQ * DIM];
__device__ bhalf g_hp0[NTASK * CH],      g_hp1[NTASK * CH],      g_hp2[NTASK * CH];
__device__ bhalf g_wi0[DIM * DIM],       g_wi1[DIM * DIM],       g_wi2[DIM * DIM];
__device__ bhalf g_wdp0[DIM * 2 * DIM],  g_wdp1[DIM * 2 * DIM],  g_wdp2[DIM * 2 * DIM];
__device__ bhalf g_wc1p0[2 * DIM * CH],  g_wc1p1[2 * DIM * CH],  g_wc1p2[2 * DIM * CH];
__device__ bhalf g_wc2p0[CH * CH],       g_wc2p1[CH * CH],       g_wc2p2[CH * CH];

__device__ __forceinline__ float gelu_f(float xval) {
    return 0.5f * xval * (1.0f + erff(xval * 0.70710678118654752440f));
}
__device__ __forceinline__ void split3(float xval, unsigned short &qs0,
                                       unsigned short &qs1, unsigned short &qs2) {
    bhalf h0 = __float2bfloat16(xval);
    float r0 = __bfloat162float(h0);
    bhalf h1 = __float2bfloat16(xval - r0);
    float r1 = __bfloat162float(h1);
    bhalf h2 = __float2bfloat16(xval - r0 - r1);
    qs0 = __bfloat16_as_ushort(h0);
    qs1 = __bfloat16_as_ushort(h1);
    qs2 = __bfloat16_as_ushort(h2);
}

__device__ __forceinline__ void ldmA(uint32_t regs[4], uint32_t addr) {
    asm volatile("ldmatrix.sync.aligned.m8n8.x4.shared.b16 {%0,%1,%2,%3}, [%4];"
        : "=r"(regs[0]), "=r"(regs[1]), "=r"(regs[2]), "=r"(regs[3]) : "r"(addr));
}
__device__ __forceinline__ void ldmBT(uint32_t regs[4], uint32_t addr) {
    asm volatile("ldmatrix.sync.aligned.m8n8.x4.trans.shared.b16 {%0,%1,%2,%3}, [%4];"
        : "=r"(regs[0]), "=r"(regs[1]), "=r"(regs[2]), "=r"(regs[3]) : "r"(addr));
}
__device__ __forceinline__ void mma16816(float cfr[4], const uint32_t afr[4],
                                         uint32_t rblo, uint32_t rbhi) {
    asm volatile(
        "mma.sync.aligned.m16n8k16.row.col.f32.bf16.bf16.f32 "
        "{%0,%1,%2,%3}, {%4,%5,%6,%7}, {%8,%9}, {%0,%1,%2,%3};"
        : "+f"(cfr[0]), "+f"(cfr[1]), "+f"(cfr[2]), "+f"(cfr[3])
        : "r"(afr[0]), "r"(afr[1]), "r"(afr[2]), "r"(afr[3]), "r"(rblo), "r"(rbhi));
}
__device__ __forceinline__ void cp16(uint32_t saddr, const void* gaddr) {
    asm volatile("cp.async.cg.shared.global [%0], [%1], 16;"
                 :: "r"(saddr), "l"(gaddr));
}
__device__ __forceinline__ void cp_commit() {
    asm volatile("cp.async.commit_group;");
}
template <int WG>
__device__ __forceinline__ void cp_wait() {
    asm volatile("cp.async.wait_group %0;" :: "n"(WG));
}

// ------------------------------ mma GEMM ------------------------------------
// Tile 128x64x32, 256 threads (8 warps, 4m x 2n), warp tile 32x32.
// 3 planes per operand, 6 cross-products; cp.async double buffer.
#define BM 128
#define BN 64
#define BK 32
#define BKP 40     // A smem row stride (bf16 elems), 80B
#define BNP 72     // B smem row stride, 144B
#define PLA (BM * BKP)            // 5120 elems per A plane
#define PLB (BK * BNP)            // 2304 elems per B plane
#define STG (3 * PLA + 3 * PLB)   // 22272 elems per stage
#define SMEM_BYTES (2 * STG * 2)  // 89088 bytes

// a_mode: 0 contiguous lda; 1 row-pool (base,rpn); 2 cat-gather (task_l/r)
// c_mode: 0 fp32 contiguous ldc; 1 fp32 row-pool split at n_split; 2 planes
__global__ __launch_bounds__(256, 2) void gemm6(
    const bhalf* __restrict__ A0, const bhalf* __restrict__ A1, const bhalf* __restrict__ A2,
    const bhalf* __restrict__ B0, const bhalf* __restrict__ B1, const bhalf* __restrict__ B2,
    const float* __restrict__ bias, float* __restrict__ Cf, float* __restrict__ Cf2,
    bhalf* __restrict__ P0, bhalf* __restrict__ P1, bhalf* __restrict__ P2,
    int K, int lda, int ldb, int ldc,
    int a_mode, int a_base, int a_rpn,
    int c_mode, int c_base, int c_rpn, int act, int n_split)
{
    extern __shared__ __align__(16) bhalf smem[];

    const int tid = threadIdx.x;
    const int lane = tid & 31, wrp = tid >> 5;
    const int m0 = blockIdx.y * BM;
    const int n0b = blockIdx.x * BN;
    const int m_w = (wrp >> 1) * 32;
    const int n_w = (wrp & 1) * 32;

    // A loader: 128 rows x 4 k-chunks(8 elems) = 512 slots, 2 per thread.
    // B loader: 32 rows x 8 n-chunks = 256 slots, 1 per thread.
    int aoffL[2], aoffR[2];
    uint32_t aswv[2];
    int akv[2];
#pragma unroll
    for (int i = 0; i < 2; i++) {
        int lin = tid + i * 256;
        int arow = lin >> 2, ak8 = (lin & 3) << 3;
        akv[i] = ak8;
        int mrow = m0 + arow;
        if (a_mode == 0) { aoffL[i] = mrow * lda + ak8; aoffR[i] = 0; }
        else if (a_mode == 1) {
            int nz = mrow / a_rpn, rr = mrow - nz * a_rpn;
            aoffL[i] = (nz * MAXR + a_base + rr) * DIM + ak8; aoffR[i] = 0;
        } else {
            int nz = mrow / BEAMK;
            aoffL[i] = (nz * MAXR + g_task_l[mrow]) * DIM + ak8;
            aoffR[i] = (nz * MAXR + g_task_r[mrow]) * DIM + ak8;
        }
        aswv[i] = (uint32_t)(arow * BKP + ak8) * 2;
    }
    const int brow = tid >> 3, bn8 = (tid & 7) << 3;
    const int boff = brow * ldb + n0b + bn8;
    const uint32_t smem_u = (uint32_t)__cvta_generic_to_shared(smem);
    const uint32_t bsw = (uint32_t)(3 * PLA + brow * BNP + bn8) * 2;

    auto issue_stage = [&](int stg, int kbase) {
        uint32_t sb = smem_u + (uint32_t)stg * (STG * 2);
#pragma unroll
        for (int i = 0; i < 2; i++) {
            int ao;
            if (a_mode == 2)
                ao = (kbase + akv[i] < DIM) ? (aoffL[i] + kbase)
                                            : (aoffR[i] + kbase - DIM);
            else
                ao = aoffL[i] + kbase;
            cp16(sb + 0 * (PLA * 2) + aswv[i], A0 + ao);
            cp16(sb + 1 * (PLA * 2) + aswv[i], A1 + ao);
            cp16(sb + 2 * (PLA * 2) + aswv[i], A2 + ao);
        }
        int bo = boff + kbase * ldb;
        cp16(sb + bsw + 0 * (PLB * 2), B0 + bo);
        cp16(sb + bsw + 1 * (PLB * 2), B1 + bo);
        cp16(sb + bsw + 2 * (PLB * 2), B2 + bo);
    };

    float acc[2][4][4];
#pragma unroll
    for (int mt = 0; mt < 2; mt++)
#pragma unroll
        for (int nt = 0; nt < 4; nt++)
#pragma unroll
            for (int qq = 0; qq < 4; qq++) acc[mt][nt][qq] = 0.f;

    const int KT = K / BK;
    issue_stage(0, 0);
    cp_commit();

    const int lrow16 = lane & 15, lcol8 = (lane >> 4) << 3;

    for (int kt = 0; kt < KT; kt++) {
        if (kt + 1 < KT) {
            issue_stage((kt + 1) & 1, (kt + 1) * BK);
            cp_commit();
            cp_wait<1>();
        } else {
            cp_wait<0>();
        }
        __syncthreads();

        uint32_t sb = smem_u + (uint32_t)(kt & 1) * (STG * 2);
#pragma unroll
        for (int ks = 0; ks < 2; ks++) {
            uint32_t frag_a[3][2][4];
            uint32_t frag_b[3][2][4];
#pragma unroll
            for (int pl = 0; pl < 3; pl++) {
#pragma unroll
                for (int mt = 0; mt < 2; mt++)
                    ldmA(frag_a[pl][mt],
                         sb + (uint32_t)(pl * PLA + (m_w + mt * 16 + lrow16) * BKP
                                         + ks * 16 + lcol8) * 2);
#pragma unroll
                for (int nb = 0; nb < 2; nb++)
                    ldmBT(frag_b[pl][nb],
                          sb + (uint32_t)(3 * PLA + pl * PLB
                                          + (ks * 16 + lrow16) * BNP
                                          + n_w + nb * 16 + lcol8) * 2);
            }
#pragma unroll
            for (int pA = 0; pA < 3; pA++) {
#pragma unroll
                for (int pB = 0; pB < 3; pB++) {
                    if (pA + pB < 3) {
#pragma unroll
                        for (int mt = 0; mt < 2; mt++)
#pragma unroll
                            for (int nt = 0; nt < 4; nt++)
                                mma16816(acc[mt][nt], frag_a[pA][mt],
                                         frag_b[pB][nt >> 1][(nt & 1) * 2],
                                         frag_b[pB][nt >> 1][(nt & 1) * 2 + 1]);
                    }
                }
            }
        }
        __syncthreads();
    }

    // ------------------------------ epilogue --------------------------------
    float* Cfx = Cf;
    int n0c = n0b;
    if (c_mode == 1 && n0b >= n_split) { Cfx = Cf2; n0c = n0b - n_split; }

    const int grp = lane >> 2, tc2 = (lane & 3) * 2;
#pragma unroll
    for (int mt = 0; mt < 2; mt++) {
#pragma unroll
        for (int nt = 0; nt < 4; nt++) {
            int coln = n_w + nt * 8 + tc2;
            float2 bv = make_float2(0.f, 0.f);
            if (bias) bv = *(const float2*)(bias + n0b + coln);
            float vals[2][2];
            vals[0][0] = acc[mt][nt][0] + bv.x; vals[0][1] = acc[mt][nt][1] + bv.y;
            vals[1][0] = acc[mt][nt][2] + bv.x; vals[1][1] = acc[mt][nt][3] + bv.y;
            if (act) {
#pragma unroll
                for (int hh = 0; hh < 2; hh++) {
                    vals[hh][0] = gelu_f(vals[hh][0]);
                    vals[hh][1] = gelu_f(vals[hh][1]);
                }
            }
#pragma unroll
            for (int hh = 0; hh < 2; hh++) {
                int mrow = m0 + m_w + mt * 16 + grp + hh * 8;
                if (c_mode == 2) {
                    size_t off = (size_t)mrow * ldc + n0b + coln;
                    unsigned short plo0, plo1, plo2, phi0, phi1, phi2;
                    split3(vals[hh][0], plo0, plo1, plo2);
                    split3(vals[hh][1], phi0, phi1, phi2);
                    *(uint32_t*)(P0 + off) = (uint32_t)plo0 | ((uint32_t)phi0 << 16);
                    *(uint32_t*)(P1 + off) = (uint32_t)plo1 | ((uint32_t)phi1 << 16);
                    *(uint32_t*)(P2 + off) = (uint32_t)plo2 | ((uint32_t)phi2 << 16);
                } else if (c_mode == 1) {
                    int nz = mrow / c_rpn, rr = mrow - nz * c_rpn;
                    float* cp = Cfx + ((size_t)nz * MAXR + c_base + rr) * DIM + n0c + coln;
                    *(float2*)cp = make_float2(vals[hh][0], vals[hh][1]);
                } else {
                    float* cp = Cfx + (size_t)mrow * ldc + n0b + coln;
                    *(float2*)cp = make_float2(vals[hh][0], vals[hh][1]);
                }
            }
        }
    }
}

// --------------------------- pack kernels -----------------------------------
__global__ void pack3_kernel(const float* __restrict__ src,
                             bhalf* __restrict__ dst0, bhalf* __restrict__ dst1,
                             bhalf* __restrict__ dst2, int nelem)
{
    for (int i = blockIdx.x * blockDim.x + threadIdx.x; i < nelem;
         i += gridDim.x * blockDim.x) {
        unsigned short qs0, qs1, qs2;
        split3(src[i], qs0, qs1, qs2);
        dst0[i] = __ushort_as_bfloat16(qs0);
        dst1[i] = __ushort_as_bfloat16(qs1);
        dst2[i] = __ushort_as_bfloat16(qs2);
    }
}
// Wd1 (1024,512) -> B' [512][1024]: B'[k][n] = Wd1[(n<512?k:512+k)][n&511]
__global__ void pack3_wd1_kernel(const float* __restrict__ src,
                                 bhalf* __restrict__ dst0, bhalf* __restrict__ dst1,
                                 bhalf* __restrict__ dst2)
{
    for (int i = blockIdx.x * blockDim.x + threadIdx.x; i < DIM * 2 * DIM;
         i += gridDim.x * blockDim.x) {
        int krow = i >> 10, ncol = i & 1023;
        float xval = src[(ncol < DIM ? krow : DIM + krow) * DIM + (ncol & (DIM - 1))];
        unsigned short qs0, qs1, qs2;
        split3(xval, qs0, qs1, qs2);
        dst0[i] = __ushort_as_bfloat16(qs0);
        dst1[i] = __ushort_as_bfloat16(qs1);
        dst2[i] = __ushort_as_bfloat16(qs2);
    }
}

// ------------------------ selection (per batch elem) ------------------------
__global__ __launch_bounds__(256) void select_kernel(
    int Bc, int S_cur, int topk, int base_dest,
    const float* __restrict__ bd1, const float* __restrict__ Wd2,
    const float* __restrict__ bd2)
{
    const int nn = blockIdx.x;
    const int tid = threadIdx.x;
    __shared__ float sw[BEAMK][SEQ];
    __shared__ int   sold[BEAMK][SEQ];
    __shared__ int   snew[BEAMK][SEQ];
    __shared__ float saccu[BEAMK];
    __shared__ float cscore[BEAMK * BEAMK];
    __shared__ int   cparent[BEAMK * BEAMK];
    __shared__ int   cpos[BEAMK * BEAMK];
    __shared__ int   ssel[BEAMK];
    __shared__ float snacc[BEAMK];
    __shared__ float sbd1[DIM];
    __shared__ float swd2[DIM];

    for (int t = tid; t < Bc * (S_cur + 1); t += 256) {
        int bb = t / (S_cur + 1), ss = t - bb * (S_cur + 1);
        sold[bb][ss] = g_idx[(nn * BEAMK + bb) * SEQ + ss];
    }
    for (int dd = tid; dd < DIM; dd += 256) { sbd1[dd] = bd1[dd]; swd2[dd] = Wd2[dd]; }
    if (tid < Bc) saccu[tid] = g_accu[nn * BEAMK + tid];
    __syncthreads();

    if (S_cur == 1) {
        if (tid < Bc) {
            g_task_l[nn * BEAMK + tid] = sold[tid][0];
            g_task_r[nn * BEAMK + tid] = sold[tid][1];
            g_idx[(nn * BEAMK + tid) * SEQ] = base_dest + tid;
        }
        return;
    }

    const int lane = tid & 31, wrp = tid >> 5;
    const float* un = g_u + (size_t)nn * MAXR * DIM;
    const float* vn = g_v + (size_t)nn * MAXR * DIM;
    for (int pp = wrp; pp < Bc * S_cur; pp += 8) {
        int bb = pp / S_cur, ss = pp - bb * S_cur;
        const float* ul = un + (size_t)sold[bb][ss] * DIM;
        const float* vr = vn + (size_t)sold[bb][ss + 1] * DIM;
        float accv = 0.f;
        for (int dd = lane; dd < DIM; dd += 32)
            accv += gelu_f(ul[dd] + vr[dd] + sbd1[dd]) * swd2[dd];
#pragma unroll
        for (int oo = 16; oo; oo >>= 1)
            accv += __shfl_xor_sync(0xffffffffu, accv, oo);
        if (lane == 0) sw[bb][ss] = accv + bd2[0];
    }
    __syncthreads();

    if (tid < Bc) {
        int bb = tid;
        float mx = -1e30f;
        for (int ss = 0; ss < S_cur; ss++) mx = fmaxf(mx, sw[bb][ss]);
        float sum = 0.f;
        for (int ss = 0; ss < S_cur; ss++) sum += expf(sw[bb][ss] - mx);
        sum += 1e-20f;
        unsigned used = 0u;
        for (int kk = 0; kk < topk; kk++) {
            float bestv = -1e30f; int besti = 0;
            for (int ss = 0; ss < S_cur; ss++) {
                if (used & (1u << ss)) continue;
                if (sw[bb][ss] > bestv) { bestv = sw[bb][ss]; besti = ss; }
            }
            used |= 1u << besti;
            float soft = expf(bestv - mx) / sum;
            cscore [bb * topk + kk] = saccu[bb] + logf(soft + 1e-20f);
            cparent[bb * topk + kk] = bb;
            cpos   [bb * topk + kk] = besti;
        }
    }
    __syncthreads();

    if (tid == 0) {
        int nc = Bc * topk;
        if (nc <= BEAMK) {
            for (int kk = 0; kk < nc; kk++) ssel[kk] = kk;
        } else {
            unsigned used = 0u;
            for (int kk = 0; kk < BEAMK; kk++) {
                float bestv = -1e30f; int besti = 0;
                for (int cc = 0; cc < nc; cc++) {
                    if (used & (1u << cc)) continue;
                    if (cscore[cc] > bestv) { bestv = cscore[cc]; besti = cc; }
                }
                used |= 1u << besti;
                ssel[kk] = besti;
            }
        }
    }
    __syncthreads();

    if (tid < BEAMK) {
        int cc = ssel[tid];
        snacc[tid] = cscore[cc];
        int pp = cparent[cc], jj = cpos[cc];
        g_task_l[nn * BEAMK + tid] = sold[pp][jj];
        g_task_r[nn * BEAMK + tid] = sold[pp][jj + 1];
    }
    __syncthreads();
    for (int t = tid; t < BEAMK * S_cur; t += 256) {
        int kk = t / S_cur, ss = t - kk * S_cur;
        int cc = ssel[kk]; int pp = cparent[cc], jj = cpos[cc];
        snew[kk][ss] = (ss < jj) ? sold[pp][ss]
                                 : (ss == jj ? base_dest + kk : sold[pp][ss + 1]);
    }
    __syncthreads();
    for (int t = tid; t < BEAMK * S_cur; t += 256) {
        int kk = t / S_cur, ss = t - kk * S_cur;
        g_idx[(nn * BEAMK + kk) * SEQ + ss] = snew[kk][ss];
    }
    if (tid < BEAMK) g_accu[nn * BEAMK + tid] = snacc[tid];
}

// ---------------------- gating + layernorm epilogue -------------------------
__global__ __launch_bounds__(256) void gate_ln_kernel(
    int base_dest, const float* __restrict__ gw, const float* __restrict__ bw)
{
    const int t = blockIdx.x;
    const int nn = t / BEAMK;
    const int kk = t - nn * BEAMK;
    const int tid = threadIdx.x;
    const float* cc   = g_cc   + (size_t)t * CH;
    const float* lrow = g_rows + ((size_t)nn * MAXR + g_task_l[t]) * DIM;
    const float* rrow = g_rows + ((size_t)nn * MAXR + g_task_r[t]) * DIM;
    __shared__ float sout[DIM];
    __shared__ float red[2][8];
    float lsum = 0.f, lsq = 0.f;
#pragma unroll
    for (int it = 0; it < 2; it++) {
        int dd = tid + it * 256;
        float c0v = cc[dd], c1v = cc[DIM + dd], c2v = cc[2 * DIM + dd], c3v = cc[3 * DIM + dd];
        float mx = fmaxf(c0v, fmaxf(c1v, c2v));
        float e0v = expf(c0v - mx), e1v = expf(c1v - mx), e2v = expf(c2v - mx);
        float inv = 1.0f / (e0v + e1v + e2v);
        float ov = (e0v * lrow[dd] + e1v * rrow[dd] + e2v * c3v) * inv;
        sout[dd] = ov; lsum += ov; lsq += ov * ov;
    }
#pragma unroll
    for (int oo = 16; oo; oo >>= 1) {
        lsum += __shfl_xor_sync(0xffffffffu, lsum, oo);
        lsq  += __shfl_xor_sync(0xffffffffu, lsq , oo);
    }
    if ((tid & 31) == 0) { red[0][tid >> 5] = lsum; red[1][tid >> 5] = lsq; }
    __syncthreads();
    if (tid < 32) {
        float ra = (tid < 8) ? red[0][tid] : 0.f;
        float rb = (tid < 8) ? red[1][tid] : 0.f;
#pragma unroll
        for (int oo = 4; oo; oo >>= 1) {
            ra += __shfl_xor_sync(0xffffffffu, ra, oo);
            rb += __shfl_xor_sync(0xffffffffu, rb, oo);
        }
        if (tid == 0) { red[0][0] = ra; red[1][0] = rb; }
    }
    __syncthreads();
    float mu   = red[0][0] * (1.0f / DIM);
    float var  = red[1][0] * (1.0f / DIM) - mu * mu;
    float rstd = rsqrtf(var + 1e-5f);
    size_t ro = ((size_t)nn * MAXR + base_dest + kk) * DIM;
#pragma unroll
    for (int it = 0; it < 2; it++) {
        int dd = tid + it * 256;
        float ov = (sout[dd] - mu) * rstd * gw[dd] + bw[dd];
        g_rows[ro + dd] = ov;
        unsigned short qs0, qs1, qs2;
        split3(ov, qs0, qs1, qs2);
        g_rp0[ro + dd] = __ushort_as_bfloat16(qs0);
        g_rp1[ro + dd] = __ushort_as_bfloat16(qs1);
        g_rp2[ro + dd] = __ushort_as_bfloat16(qs2);
    }
}

// --------------------- init: layernorm of x@Wi+bi ---------------------------
__global__ __launch_bounds__(256) void ln_init_kernel(
    const float* __restrict__ gw, const float* __restrict__ bw)
{
    const int t = blockIdx.x;
    const int nn = t >> 5, ss = t & 31;
    const int tid = threadIdx.x;
    const float* inp = g_tmp + (size_t)t * DIM;
    size_t ro = ((size_t)nn * MAXR + ss) * DIM;
    __shared__ float red[2][8];
    float v0 = inp[tid], v1 = inp[tid + 256];
    float lsum = v0 + v1, lsq = v0 * v0 + v1 * v1;
#pragma unroll
    for (int oo = 16; oo; oo >>= 1) {
        lsum += __shfl_xor_sync(0xffffffffu, lsum, oo);
        lsq  += __shfl_xor_sync(0xffffffffu, lsq , oo);
    }
    if ((tid & 31) == 0) { red[0][tid >> 5] = lsum; red[1][tid >> 5] = lsq; }
    __syncthreads();
    if (tid < 32) {
        float ra = (tid < 8) ? red[0][tid] : 0.f;
        float rb = (tid < 8) ? red[1][tid] : 0.f;
#pragma unroll
        for (int oo = 4; oo; oo >>= 1) {
            ra += __shfl_xor_sync(0xffffffffu, ra, oo);
            rb += __shfl_xor_sync(0xffffffffu, rb, oo);
        }
        if (tid == 0) { red[0][0] = ra; red[1][0] = rb; }
    }
    __syncthreads();
    float mu   = red[0][0] * (1.0f / DIM);
    float var  = red[1][0] * (1.0f / DIM) - mu * mu;
    float rstd = rsqrtf(var + 1e-5f);
#pragma unroll
    for (int it = 0; it < 2; it++) {
        int dd = tid + it * 256;
        float vv = it ? v1 : v0;
        float ov = (vv - mu) * rstd * gw[dd] + bw[dd];
        g_rows[ro + dd] = ov;
        unsigned short qs0, qs1, qs2;
        split3(ov, qs0, qs1, qs2);
        g_rp0[ro + dd] = __ushort_as_bfloat16(qs0);
        g_rp1[ro + dd] = __ushort_as_bfloat16(qs1);
        g_rp2[ro + dd] = __ushort_as_bfloat16(qs2);
    }
}

__global__ void init_state_kernel()
{
    int nn = blockIdx.x;
    if (threadIdx.x < SEQ) g_idx[nn * BEAMK * SEQ + threadIdx.x] = threadIdx.x;
    if (threadIdx.x == 0) g_accu[nn * BEAMK] = 0.f;
}

__global__ __launch_bounds__(256) void final_kernel(float* __restrict__ outp)
{
    const int nn = blockIdx.x;
    const int tid = threadIdx.x;
    __shared__ float wts[BEAMK];
    __shared__ int   rid[BEAMK];
    if (tid < BEAMK) rid[tid] = g_idx[(nn * BEAMK + tid) * SEQ];
    if (tid == 0) {
        float av[BEAMK]; float mx = -1e30f;
        for (int bb = 0; bb < BEAMK; bb++) {
            av[bb] = g_accu[nn * BEAMK + bb]; mx = fmaxf(mx, av[bb]);
        }
        float sm = 0.f;
        for (int bb = 0; bb < BEAMK; bb++) { av[bb] = expf(av[bb] - mx); sm += av[bb]; }
        for (int bb = 0; bb < BEAMK; bb++) wts[bb] = av[bb] / sm;
    }
    __syncthreads();
#pragma unroll
    for (int it = 0; it < 2; it++) {
        int dd = tid + it * 256;
        float accv = 0.f;
        for (int bb = 0; bb < BEAMK; bb++)
            accv += wts[bb] * g_rows[((size_t)nn * MAXR + rid[bb]) * DIM + dd];
        outp[nn * DIM + dd] = accv;
    }
}

// --------------------------------- host ------------------------------------
extern "C" void kernel_launch(void* const* d_in, const int* in_sizes, int n_in,
                              void* d_out, int out_size)
{
    const float* x   = (const float*)d_in[0];
    const float* Wi  = (const float*)d_in[2];
    const float* bi  = (const float*)d_in[3];
    const float* g1  = (const float*)d_in[4];
    const float* b1  = (const float*)d_in[5];
    const float* Wd1 = (const float*)d_in[6];
    const float* bd1 = (const float*)d_in[7];
    const float* Wd2 = (const float*)d_in[8];
    const float* bd2 = (const float*)d_in[9];
    const float* Wc1 = (const float*)d_in[10];
    const float* bc1 = (const float*)d_in[11];
    const float* Wc2 = (const float*)d_in[12];
    const float* bc2 = (const float*)d_in[13];
    const float* g2  = (const float*)d_in[14];
    const float* b2  = (const float*)d_in[15];
    float* outp = (float*)d_out;

    cudaFuncSetAttribute(gemm6, cudaFuncAttributeMaxDynamicSharedMemorySize,
                         SMEM_BYTES);

    float *tmp_p, *u_p, *v_p, *cc_p;
    cudaGetSymbolAddress((void**)&tmp_p, g_tmp);
    cudaGetSymbolAddress((void**)&u_p,   g_u);
    cudaGetSymbolAddress((void**)&v_p,   g_v);
    cudaGetSymbolAddress((void**)&cc_p,  g_cc);
    bhalf *rp0, *rp1, *rp2, *xp0, *xp1, *xp2, *hp0, *hp1, *hp2;
    bhalf *wi0, *wi1, *wi2, *wd0, *wd1p, *wd2p;
    bhalf *wc10, *wc11, *wc12, *wc20, *wc21, *wc22;
    cudaGetSymbolAddress((void**)&rp0, g_rp0);
    cudaGetSymbolAddress((void**)&rp1, g_rp1);
    cudaGetSymbolAddress((void**)&rp2, g_rp2);
    cudaGetSymbolAddress((void**)&xp0, g_xp0);
    cudaGetSymbolAddress((void**)&xp1, g_xp1);
    cudaGetSymbolAddress((void**)&xp2, g_xp2);
    cudaGetSymbolAddress((void**)&hp0, g_hp0);
    cudaGetSymbolAddress((void**)&hp1, g_hp1);
    cudaGetSymbolAddress((void**)&hp2, g_hp2);
    cudaGetSymbolAddress((void**)&wi0, g_wi0);
    cudaGetSymbolAddress((void**)&wi1, g_wi1);
    cudaGetSymbolAddress((void**)&wi2, g_wi2);
    cudaGetSymbolAddress((void**)&wd0,  g_wdp0);
    cudaGetSymbolAddress((void**)&wd1p, g_wdp1);
    cudaGetSymbolAddress((void**)&wd2p, g_wdp2);
    cudaGetSymbolAddress((void**)&wc10, g_wc1p0);
    cudaGetSymbolAddress((void**)&wc11, g_wc1p1);
    cudaGetSymbolAddress((void**)&wc12, g_wc1p2);
    cudaGetSymbolAddress((void**)&wc20, g_wc2p0);
    cudaGetSymbolAddress((void**)&wc21, g_wc2p1);
    cudaGetSymbolAddress((void**)&wc22, g_wc2p2);

    // pack inputs & weights into 3-split planes
    pack3_kernel<<<512, 256>>>(x,   xp0, xp1, xp2, NB * SEQ * DIM);
    pack3_kernel<<<256, 256>>>(Wi,  wi0, wi1, wi2, DIM * DIM);
    pack3_wd1_kernel<<<256, 256>>>(Wd1, wd0, wd1p, wd2p);
    pack3_kernel<<<512, 256>>>(Wc1, wc10, wc11, wc12, 2 * DIM * CH);
    pack3_kernel<<<512, 256>>>(Wc2, wc20, wc21, wc22, CH * CH);

    dim3 blk(256);
    // init GEMM: tmp = x@Wi+bi  (M=8192, N=512, K=512)
    gemm6<<<dim3(DIM / BN, (NB * SEQ) / BM), blk, SMEM_BYTES>>>(
        xp0, xp1, xp2, wi0, wi1, wi2, bi, tmp_p, nullptr,
        nullptr, nullptr, nullptr,
        DIM, DIM, DIM, DIM, 0, 0, 0, 0, 0, 0, 0, 0);
    ln_init_kernel<<<NB * SEQ, 256>>>(g1, b1);
    init_state_kernel<<<NB, 32>>>();
    // u|v projection of initial rows (M=8192, N=1024, K=512)
    gemm6<<<dim3(2 * DIM / BN, (NB * SEQ) / BM), blk, SMEM_BYTES>>>(
        rp0, rp1, rp2, wd0, wd1p, wd2p, nullptr, u_p, v_p,
        nullptr, nullptr, nullptr,
        DIM, 0, 2 * DIM, DIM, 1, 0, SEQ, 1, 0, SEQ, 0, DIM);

    for (int step = 0; step < SEQ - 1; step++) {
        int S_cur = (SEQ - 1) - step;
        int Bc = (step == 0) ? 1 : BEAMK;
        int topk = S_cur < BEAMK ? S_cur : BEAMK;
        int base = SEQ + step * BEAMK;

        select_kernel<<<NB, 256>>>(Bc, S_cur, topk, base, bd1, Wd2, bd2);
        // cat GEMM: gelu([l|r]@Wc1+bc1) -> hcat planes (M=1280,N=2048,K=1024)
        gemm6<<<dim3(CH / BN, NTASK / BM), blk, SMEM_BYTES>>>(
            rp0, rp1, rp2, wc10, wc11, wc12, bc1, nullptr, nullptr,
            hp0, hp1, hp2,
            2 * DIM, 0, CH, CH, 2, 0, 0, 2, 0, 0, 1, 0);
        // GEMM2: cc = hcat@Wc2+bc2  (M=1280, N=2048, K=2048)
        gemm6<<<dim3(CH / BN, NTASK / BM), blk, SMEM_BYTES>>>(
            hp0, hp1, hp2, wc20, wc21, wc22, bc2, cc_p, nullptr,
            nullptr, nullptr, nullptr,
            CH, CH, CH, CH, 0, 0, 0, 0, 0, 0, 0, 0);
        gate_ln_kernel<<<NTASK, 256>>>(base, g2, b2);
        if (step < SEQ - 2) {
            // u|v projection of new rows (M=1280, N=1024, K=512)
            gemm6<<<dim3(2 * DIM / BN, NTASK / BM), blk, SMEM_BYTES>>>(
                rp0, rp1, rp2, wd0, wd1p, wd2p, nullptr, u_p, v_p,
                nullptr, nullptr, nullptr,
                DIM, 0, 2 * DIM, DIM, 1, base, BEAMK, 1, base, BEAMK, 0, DIM);
        }
    }

    final_kernel<<<NB, 256>>>(outp);
    (void)in_sizes; (void)n_in; (void)out_size;
}